// round 15
// baseline (speedup 1.0000x reference)
#include <cuda_runtime.h>
#include <cuda_bf16.h>
#include <cstdint>

// Problem constants (fixed by the dataset)
#define CS   256
#define CN   558
#define CB2  8192
#define CF   128
#define CM   (CS * CN)      // 142848
#define CE   (CS * CB2)     // 2097152
#define CAP  128            // CSR capacity per destination (in-degree ~11)

#define NCHUNK 4
#define SCHUNK (CS / NCHUNK)          // 64 samples per chunk
#define MCHUNK (SCHUNK * CN)          // 35712 rows per chunk

// ---------------------------------------------------------------------------
// Scratch
// ---------------------------------------------------------------------------
__device__ float    g_xw[(size_t)CM * CF];
__device__ float    g_deg[CM];
__device__ float    g_dinv[CM];
__device__ int      g_cnt[CM];
__device__ int2     g_rec[(size_t)CM * CAP];   // {row, bits(bd)}
__device__ unsigned g_bdmax_bits;              // idempotent across replays
__device__ uint4    g_wh4[2048];               // W hi plane, swizzled (32KB)
__device__ uint4    g_wl4[2048];               // W lo plane, swizzled (32KB)

// ---------------------------------------------------------------------------
// helpers
// ---------------------------------------------------------------------------
__device__ __forceinline__ unsigned smem_u32(const void* p) {
    unsigned a;
    asm("{ .reg .u64 t; cvta.to.shared.u64 t, %1; cvt.u32.u64 %0, t; }" : "=r"(a) : "l"(p));
    return a;
}
__device__ __forceinline__ uint4 ldsm4(unsigned addr) {
    uint4 v;
    asm volatile("ldmatrix.sync.aligned.m8n8.x4.shared.b16 {%0,%1,%2,%3}, [%4];"
                 : "=r"(v.x), "=r"(v.y), "=r"(v.z), "=r"(v.w) : "r"(addr));
    return v;
}
__device__ __forceinline__ void mma_bf16(float* d, uint4 a, unsigned b0, unsigned b1) {
    asm volatile(
        "mma.sync.aligned.m16n8k16.row.col.f32.bf16.bf16.f32 "
        "{%0,%1,%2,%3}, {%4,%5,%6,%7}, {%8,%9}, {%0,%1,%2,%3};"
        : "+f"(d[0]), "+f"(d[1]), "+f"(d[2]), "+f"(d[3])
        : "r"(a.x), "r"(a.y), "r"(a.z), "r"(a.w), "r"(b0), "r"(b1));
}
__device__ __forceinline__ int swz(int r, int chunk) {
    return r * 256 + ((chunk ^ (r & 7)) << 4);
}

// ---------------------------------------------------------------------------
// 1) W prep (idempotent)
// ---------------------------------------------------------------------------
__global__ void k_wprep(const float* __restrict__ Wm) {
    int p = blockIdx.x * blockDim.x + threadIdx.x;
    if (p >= 128 * 64) return;
    int r  = p >> 6;
    int kp = p & 63;
    float2 f = __ldg((const float2*)Wm + (size_t)r * 64 + kp);
    __nv_bfloat16 h0 = __float2bfloat16_rn(f.x);
    __nv_bfloat16 h1 = __float2bfloat16_rn(f.y);
    __nv_bfloat16 l0 = __float2bfloat16_rn(f.x - __bfloat162float(h0));
    __nv_bfloat16 l1 = __float2bfloat16_rn(f.y - __bfloat162float(h1));
    unsigned hh = ((unsigned)__bfloat16_as_ushort(h1) << 16) | __bfloat16_as_ushort(h0);
    unsigned ll = ((unsigned)__bfloat16_as_ushort(l1) << 16) | __bfloat16_as_ushort(l0);
    int byte = swz(r, kp >> 2) + ((kp & 3) << 2);
    *(unsigned*)((char*)g_wh4 + byte) = hh;
    *(unsigned*)((char*)g_wl4 + byte) = ll;
}

// ---------------------------------------------------------------------------
// 2) build, CTA-per-sample (no global atomics)
// ---------------------------------------------------------------------------
__global__ void __launch_bounds__(1024) k_build(const int* __restrict__ ei,
                                                const float* __restrict__ bd) {
    __shared__ int   scnt[CN];
    __shared__ float sdeg[CN];
    __shared__ float smax[32];

    int s   = blockIdx.x;
    int tid = threadIdx.x;
    int base = s * CN;

    for (int n = tid; n < CN; n += 1024) { scnt[n] = 0; sdeg[n] = 0.0f; }
    __syncthreads();

    const int* srcp = ei + (size_t)s * 2 * CB2;
    const int* dstp = srcp + CB2;
    const float* bdp = bd + (size_t)s * CB2;

    float v = 0.0f;
    #pragma unroll
    for (int t = 0; t < CB2 / 1024; t++) {
        int e   = tid + t * 1024;
        int src = __ldg(srcp + e);
        int dst = __ldg(dstp + e);
        if (src != dst) {
            float bdv = __ldg(bdp + e);
            v = fmaxf(v, bdv);
            atomicAdd(&sdeg[dst], bdv);
            int idx = atomicAdd(&scnt[dst], 1);
            if (idx < CAP)
                g_rec[(size_t)(base + dst) * CAP + idx] =
                    make_int2(base + src, __float_as_int(bdv));
        }
    }

    #pragma unroll
    for (int o = 16; o > 0; o >>= 1)
        v = fmaxf(v, __shfl_xor_sync(0xffffffffu, v, o));
    int lane = tid & 31, wid = tid >> 5;
    if (lane == 0) smax[wid] = v;
    __syncthreads();
    if (wid == 0) {
        v = smax[lane];
        #pragma unroll
        for (int o = 16; o > 0; o >>= 1)
            v = fmaxf(v, __shfl_xor_sync(0xffffffffu, v, o));
        if (lane == 0) atomicMax(&g_bdmax_bits, __float_as_uint(v));
    }

    for (int n = tid; n < CN; n += 1024) {
        g_cnt[base + n] = scnt[n];
        g_deg[base + n] = sdeg[n];
    }
}

// ---------------------------------------------------------------------------
// 3) dinv = rsqrt(1 + deg/bd_max)
// ---------------------------------------------------------------------------
__global__ void k_dinv() {
    int i = blockIdx.x * blockDim.x + threadIdx.x;
    if (i >= CM) return;
    float bm = __uint_as_float(g_bdmax_bits);
    g_dinv[i] = rsqrtf(1.0f + g_deg[i] / bm);
}

// ---------------------------------------------------------------------------
// 4) xw = x @ W^T via mma.sync bf16, 3-term split. Chunked by m-offset.
// ---------------------------------------------------------------------------
#define SM_AH 0
#define SM_AL 16384
#define SM_WH 32768
#define SM_WL 65536
#define SM_TOT 98304

__global__ void __launch_bounds__(128) k_gemm(const float* __restrict__ x,
                                              int mbase) {
    extern __shared__ char smem[];
    int tid = threadIdx.x, wid = tid >> 5, lane = tid & 31;
    size_t m0 = (size_t)mbase + (size_t)blockIdx.x * 64;

    {
        uint4* dWh = (uint4*)(smem + SM_WH);
        uint4* dWl = (uint4*)(smem + SM_WL);
        #pragma unroll
        for (int i = 0; i < 16; i++) {
            dWh[tid + i * 128] = g_wh4[tid + i * 128];
            dWl[tid + i * 128] = g_wl4[tid + i * 128];
        }
    }
    {
        char* th = smem + SM_AH;
        char* tl = smem + SM_AL;
        const float2* gx = (const float2*)(x + m0 * CF);
        #pragma unroll
        for (int t = 0; t < 32; t++) {
            int p  = tid + t * 128;
            int r  = p >> 6;
            int kp = p & 63;
            float2 f = __ldg(gx + (size_t)r * 64 + kp);
            __nv_bfloat16 h0 = __float2bfloat16_rn(f.x);
            __nv_bfloat16 h1 = __float2bfloat16_rn(f.y);
            __nv_bfloat16 l0 = __float2bfloat16_rn(f.x - __bfloat162float(h0));
            __nv_bfloat16 l1 = __float2bfloat16_rn(f.y - __bfloat162float(h1));
            unsigned hh = ((unsigned)__bfloat16_as_ushort(h1) << 16) | __bfloat16_as_ushort(h0);
            unsigned ll = ((unsigned)__bfloat16_as_ushort(l1) << 16) | __bfloat16_as_ushort(l0);
            int byte = swz(r, kp >> 2) + ((kp & 3) << 2);
            *(unsigned*)(th + byte) = hh;
            *(unsigned*)(tl + byte) = ll;
        }
    }
    __syncthreads();

    unsigned sAh = smem_u32(smem + SM_AH);
    unsigned sAl = smem_u32(smem + SM_AL);
    unsigned sWh = smem_u32(smem + SM_WH);
    unsigned sWl = smem_u32(smem + SM_WL);

    int rbase = wid * 16;
    float acc[16][4];
    #pragma unroll
    for (int j = 0; j < 16; j++)
        #pragma unroll
        for (int c = 0; c < 4; c++) acc[j][c] = 0.0f;

    int am = lane >> 3;
    int ar = rbase + ((am & 1) << 3) + (lane & 7);
    int ac_off = am >> 1;
    int bm_ = lane >> 3;
    int br_off = ((bm_ >> 1) << 3) + (lane & 7);
    int bc_off = bm_ & 1;

    #pragma unroll
    for (int ks = 0; ks < 8; ks++) {
        uint4 ah = ldsm4(sAh + swz(ar, ks * 2 + ac_off));
        uint4 al = ldsm4(sAl + swz(ar, ks * 2 + ac_off));
        #pragma unroll
        for (int i = 0; i < 8; i++) {
            int brow = i * 16 + br_off;
            uint4 bh = ldsm4(sWh + swz(brow, ks * 2 + bc_off));
            mma_bf16(acc[2 * i],     ah, bh.x, bh.y);
            mma_bf16(acc[2 * i + 1], ah, bh.z, bh.w);
            mma_bf16(acc[2 * i],     al, bh.x, bh.y);
            mma_bf16(acc[2 * i + 1], al, bh.z, bh.w);
            uint4 bl = ldsm4(sWl + swz(brow, ks * 2 + bc_off));
            mma_bf16(acc[2 * i],     ah, bl.x, bl.y);
            mma_bf16(acc[2 * i + 1], ah, bl.z, bl.w);
        }
    }

    int erow = rbase + (lane >> 2);
    int ecol = (lane & 3) * 2;
    #pragma unroll
    for (int j = 0; j < 16; j++) {
        float* p0 = g_xw + (m0 + erow) * CF + j * 8 + ecol;
        p0[0] = acc[j][0];
        p0[1] = acc[j][1];
        float* p1 = p0 + 8 * CF;
        p1[0] = acc[j][2];
        p1[1] = acc[j][3];
    }
}

// ---------------------------------------------------------------------------
// 5) gather (chunked by node offset; fp32, x4-unrolled inner loop)
// ---------------------------------------------------------------------------
__global__ void __launch_bounds__(256) k_agg(const float* __restrict__ bias,
                                             float* __restrict__ out,
                                             int nbase) {
    int wg   = nbase + ((blockIdx.x * blockDim.x + threadIdx.x) >> 5);
    int lane = threadIdx.x & 31;

    const float4* xw4 = (const float4*)g_xw;
    float dc  = g_dinv[wg];
    float ibm = 1.0f / __uint_as_float(g_bdmax_bits);
    int   deg = min(g_cnt[wg], CAP);

    float4 xv = __ldg(xw4 + (size_t)wg * 32 + lane);
    float4 acc;
    acc.x = dc * xv.x; acc.y = dc * xv.y; acc.z = dc * xv.z; acc.w = dc * xv.w;

    const int2* r = g_rec + (size_t)wg * CAP;
    for (int e0 = 0; e0 < deg; e0 += 32) {
        int idx = e0 + lane;
        int2 rc = make_int2(0, 0);
        if (idx < deg) rc = __ldg(r + idx);
        int nv = min(32, deg - e0);
        int j = 0;
        for (; j + 4 <= nv; j += 4) {
            int   r0 = __shfl_sync(0xffffffffu, rc.x, j);
            int   r1 = __shfl_sync(0xffffffffu, rc.x, j + 1);
            int   r2 = __shfl_sync(0xffffffffu, rc.x, j + 2);
            int   r3 = __shfl_sync(0xffffffffu, rc.x, j + 3);
            float b0 = __int_as_float(__shfl_sync(0xffffffffu, rc.y, j));
            float b1 = __int_as_float(__shfl_sync(0xffffffffu, rc.y, j + 1));
            float b2 = __int_as_float(__shfl_sync(0xffffffffu, rc.y, j + 2));
            float b3 = __int_as_float(__shfl_sync(0xffffffffu, rc.y, j + 3));
            float d0 = __ldg(&g_dinv[r0]);
            float d1 = __ldg(&g_dinv[r1]);
            float d2 = __ldg(&g_dinv[r2]);
            float d3 = __ldg(&g_dinv[r3]);
            float4 v0 = __ldg(xw4 + (size_t)r0 * 32 + lane);
            float4 v1 = __ldg(xw4 + (size_t)r1 * 32 + lane);
            float4 v2 = __ldg(xw4 + (size_t)r2 * 32 + lane);
            float4 v3 = __ldg(xw4 + (size_t)r3 * 32 + lane);
            float w0 = d0 * (b0 * ibm);
            float w1 = d1 * (b1 * ibm);
            float w2 = d2 * (b2 * ibm);
            float w3 = d3 * (b3 * ibm);
            acc.x += w0 * v0.x; acc.y += w0 * v0.y; acc.z += w0 * v0.z; acc.w += w0 * v0.w;
            acc.x += w1 * v1.x; acc.y += w1 * v1.y; acc.z += w1 * v1.z; acc.w += w1 * v1.w;
            acc.x += w2 * v2.x; acc.y += w2 * v2.y; acc.z += w2 * v2.z; acc.w += w2 * v2.w;
            acc.x += w3 * v3.x; acc.y += w3 * v3.y; acc.z += w3 * v3.z; acc.w += w3 * v3.w;
        }
        for (; j < nv; j++) {
            int   row = __shfl_sync(0xffffffffu, rc.x, j);
            float bdv = __int_as_float(__shfl_sync(0xffffffffu, rc.y, j));
            float w2  = __ldg(&g_dinv[row]) * (bdv * ibm);
            float4 v  = __ldg(xw4 + (size_t)row * 32 + lane);
            acc.x += w2 * v.x; acc.y += w2 * v.y;
            acc.z += w2 * v.z; acc.w += w2 * v.w;
        }
    }

    float4 b4 = __ldg(((const float4*)bias) + lane);
    float4 o;
    o.x = dc * acc.x + b4.x;
    o.y = dc * acc.y + b4.y;
    o.z = dc * acc.z + b4.z;
    o.w = dc * acc.w + b4.w;
    ((float4*)out)[(size_t)wg * 32 + lane] = o;
}

// ---------------------------------------------------------------------------
// Launch: chunked software pipeline across two streams.
//   s1: wprep -> gemm(0..3), event after each chunk
//   s0: build -> dinv -> { wait eG[c]; agg(c) } for c = 0..3
// ---------------------------------------------------------------------------
extern "C" void kernel_launch(void* const* d_in, const int* in_sizes, int n_in,
                              void* d_out, int out_size) {
    const float* x    = (const float*)d_in[0];
    const int*   ei   = (const int*)d_in[1];
    const float* bd   = (const float*)d_in[2];
    const float* Wm   = (const float*)d_in[3];
    const float* bias = (const float*)d_in[4];
    float*       out  = (float*)d_out;
    (void)in_sizes; (void)n_in; (void)out_size;

    static cudaStream_t s1 = nullptr;
    static cudaEvent_t  eFork = nullptr;
    static cudaEvent_t  eG[NCHUNK] = {};
    static bool configured = false;
    if (!configured) {
        cudaStreamCreateWithFlags(&s1, cudaStreamNonBlocking);
        cudaEventCreateWithFlags(&eFork, cudaEventDisableTiming);
        for (int c = 0; c < NCHUNK; c++)
            cudaEventCreateWithFlags(&eG[c], cudaEventDisableTiming);
        cudaFuncSetAttribute(k_gemm, cudaFuncAttributeMaxDynamicSharedMemorySize, SM_TOT);
        configured = true;
    }

    cudaEventRecord(eFork, 0);
    cudaStreamWaitEvent(s1, eFork, 0);

    // arm B (s1): feature transform, chunked
    k_wprep<<<32, 256, 0, s1>>>(Wm);
    for (int c = 0; c < NCHUNK; c++) {
        k_gemm<<<MCHUNK / 64, 128, SM_TOT, s1>>>(x, c * MCHUNK);
        cudaEventRecord(eG[c], s1);
    }

    // arm A (caller stream): graph normalization, then pipelined gather
    k_build<<<CS, 1024>>>(ei, bd);
    k_dinv <<<(CM + 255) / 256, 256>>>();
    for (int c = 0; c < NCHUNK; c++) {
        cudaStreamWaitEvent(0, eG[c], 0);
        k_agg<<<MCHUNK * 32 / 256, 256>>>(bias, out, c * MCHUNK);
    }
}

// round 16
// speedup vs baseline: 1.1042x; 1.1042x over previous
#include <cuda_runtime.h>
#include <cuda_bf16.h>
#include <cstdint>

// Problem constants (fixed by the dataset)
#define CS   256
#define CN   558
#define CB2  8192
#define CF   128
#define CM   (CS * CN)      // 142848
#define CE   (CS * CB2)     // 2097152
#define CAP  128            // CSR capacity per destination (in-degree ~11)

// ---------------------------------------------------------------------------
// Scratch
// ---------------------------------------------------------------------------
__device__ float    g_xw[(size_t)CM * CF];
__device__ float    g_deg[CM];
__device__ float    g_dinv[CM];
__device__ int      g_cnt[CM];
__device__ int2     g_rec[(size_t)CM * CAP];   // {row, bits(bd)}
__device__ unsigned g_bdmax_bits;              // idempotent across replays
__device__ uint4    g_wh4[2048];               // W hi plane, swizzled (32KB)
__device__ uint4    g_wl4[2048];               // W lo plane, swizzled (32KB)

// ---------------------------------------------------------------------------
// helpers
// ---------------------------------------------------------------------------
__device__ __forceinline__ unsigned smem_u32(const void* p) {
    unsigned a;
    asm("{ .reg .u64 t; cvta.to.shared.u64 t, %1; cvt.u32.u64 %0, t; }" : "=r"(a) : "l"(p));
    return a;
}
__device__ __forceinline__ uint4 ldsm4(unsigned addr) {
    uint4 v;
    asm volatile("ldmatrix.sync.aligned.m8n8.x4.shared.b16 {%0,%1,%2,%3}, [%4];"
                 : "=r"(v.x), "=r"(v.y), "=r"(v.z), "=r"(v.w) : "r"(addr));
    return v;
}
__device__ __forceinline__ void mma_bf16(float* d, uint4 a, unsigned b0, unsigned b1) {
    asm volatile(
        "mma.sync.aligned.m16n8k16.row.col.f32.bf16.bf16.f32 "
        "{%0,%1,%2,%3}, {%4,%5,%6,%7}, {%8,%9}, {%0,%1,%2,%3};"
        : "+f"(d[0]), "+f"(d[1]), "+f"(d[2]), "+f"(d[3])
        : "r"(a.x), "r"(a.y), "r"(a.z), "r"(a.w), "r"(b0), "r"(b1));
}
__device__ __forceinline__ int swz(int r, int chunk) {
    return r * 256 + ((chunk ^ (r & 7)) << 4);
}

// ---------------------------------------------------------------------------
// 1) W prep (idempotent)
// ---------------------------------------------------------------------------
__global__ void k_wprep(const float* __restrict__ Wm) {
    int p = blockIdx.x * blockDim.x + threadIdx.x;
    if (p >= 128 * 64) return;
    int r  = p >> 6;
    int kp = p & 63;
    float2 f = __ldg((const float2*)Wm + (size_t)r * 64 + kp);
    __nv_bfloat16 h0 = __float2bfloat16_rn(f.x);
    __nv_bfloat16 h1 = __float2bfloat16_rn(f.y);
    __nv_bfloat16 l0 = __float2bfloat16_rn(f.x - __bfloat162float(h0));
    __nv_bfloat16 l1 = __float2bfloat16_rn(f.y - __bfloat162float(h1));
    unsigned hh = ((unsigned)__bfloat16_as_ushort(h1) << 16) | __bfloat16_as_ushort(h0);
    unsigned ll = ((unsigned)__bfloat16_as_ushort(l1) << 16) | __bfloat16_as_ushort(l0);
    int byte = swz(r, kp >> 2) + ((kp & 3) << 2);
    *(unsigned*)((char*)g_wh4 + byte) = hh;
    *(unsigned*)((char*)g_wl4 + byte) = ll;
}

// ---------------------------------------------------------------------------
// 2) build, CTA-per-sample (no global atomics)
// ---------------------------------------------------------------------------
__global__ void __launch_bounds__(1024) k_build(const int* __restrict__ ei,
                                                const float* __restrict__ bd) {
    __shared__ int   scnt[CN];
    __shared__ float sdeg[CN];
    __shared__ float smax[32];

    int s   = blockIdx.x;
    int tid = threadIdx.x;
    int base = s * CN;

    for (int n = tid; n < CN; n += 1024) { scnt[n] = 0; sdeg[n] = 0.0f; }
    __syncthreads();

    const int* srcp = ei + (size_t)s * 2 * CB2;
    const int* dstp = srcp + CB2;
    const float* bdp = bd + (size_t)s * CB2;

    float v = 0.0f;
    #pragma unroll
    for (int t = 0; t < CB2 / 1024; t++) {
        int e   = tid + t * 1024;
        int src = __ldg(srcp + e);
        int dst = __ldg(dstp + e);
        if (src != dst) {
            float bdv = __ldg(bdp + e);
            v = fmaxf(v, bdv);
            atomicAdd(&sdeg[dst], bdv);
            int idx = atomicAdd(&scnt[dst], 1);
            if (idx < CAP)
                g_rec[(size_t)(base + dst) * CAP + idx] =
                    make_int2(base + src, __float_as_int(bdv));
        }
    }

    #pragma unroll
    for (int o = 16; o > 0; o >>= 1)
        v = fmaxf(v, __shfl_xor_sync(0xffffffffu, v, o));
    int lane = tid & 31, wid = tid >> 5;
    if (lane == 0) smax[wid] = v;
    __syncthreads();
    if (wid == 0) {
        v = smax[lane];
        #pragma unroll
        for (int o = 16; o > 0; o >>= 1)
            v = fmaxf(v, __shfl_xor_sync(0xffffffffu, v, o));
        if (lane == 0) atomicMax(&g_bdmax_bits, __float_as_uint(v));
    }

    for (int n = tid; n < CN; n += 1024) {
        g_cnt[base + n] = scnt[n];
        g_deg[base + n] = sdeg[n];
    }
}

// ---------------------------------------------------------------------------
// 3) dinv = rsqrt(1 + deg/bd_max)
// ---------------------------------------------------------------------------
__global__ void k_dinv() {
    int i = blockIdx.x * blockDim.x + threadIdx.x;
    if (i >= CM) return;
    float bm = __uint_as_float(g_bdmax_bits);
    g_dinv[i] = rsqrtf(1.0f + g_deg[i] / bm);
}

// ---------------------------------------------------------------------------
// 4) xw = x @ W^T via mma.sync bf16, 3-term split.
//    CTA = 64 rows, 4 warps in a 2x2 grid; warp tile = 32 rows x 64 cols
//    (cuts per-warp LDSM traffic 33% vs 16x128 tiles; same MMA count).
// ---------------------------------------------------------------------------
#define SM_AH 0
#define SM_AL 16384
#define SM_WH 32768
#define SM_WL 65536
#define SM_TOT 98304

__global__ void __launch_bounds__(128) k_gemm(const float* __restrict__ x) {
    extern __shared__ char smem[];
    int tid = threadIdx.x, wid = tid >> 5, lane = tid & 31;
    size_t m0 = (size_t)blockIdx.x * 64;

    {
        uint4* dWh = (uint4*)(smem + SM_WH);
        uint4* dWl = (uint4*)(smem + SM_WL);
        #pragma unroll
        for (int i = 0; i < 16; i++) {
            dWh[tid + i * 128] = g_wh4[tid + i * 128];
            dWl[tid + i * 128] = g_wl4[tid + i * 128];
        }
    }
    {
        char* th = smem + SM_AH;
        char* tl = smem + SM_AL;
        const float2* gx = (const float2*)(x + m0 * CF);
        #pragma unroll
        for (int t = 0; t < 32; t++) {
            int p  = tid + t * 128;
            int r  = p >> 6;
            int kp = p & 63;
            float2 f = __ldg(gx + (size_t)r * 64 + kp);
            __nv_bfloat16 h0 = __float2bfloat16_rn(f.x);
            __nv_bfloat16 h1 = __float2bfloat16_rn(f.y);
            __nv_bfloat16 l0 = __float2bfloat16_rn(f.x - __bfloat162float(h0));
            __nv_bfloat16 l1 = __float2bfloat16_rn(f.y - __bfloat162float(h1));
            unsigned hh = ((unsigned)__bfloat16_as_ushort(h1) << 16) | __bfloat16_as_ushort(h0);
            unsigned ll = ((unsigned)__bfloat16_as_ushort(l1) << 16) | __bfloat16_as_ushort(l0);
            int byte = swz(r, kp >> 2) + ((kp & 3) << 2);
            *(unsigned*)(th + byte) = hh;
            *(unsigned*)(tl + byte) = ll;
        }
    }
    __syncthreads();

    unsigned sAh = smem_u32(smem + SM_AH);
    unsigned sAl = smem_u32(smem + SM_AL);
    unsigned sWh = smem_u32(smem + SM_WH);
    unsigned sWl = smem_u32(smem + SM_WL);

    int wrow = (wid & 1) * 32;     // warp row base (0 or 32)
    int wcol = (wid >> 1) * 64;    // warp col base (0 or 64)

    // acc[t*8 + i*2 + h]: t = A 16-row tile (0,1), i = B 16-col group (0..3),
    //                     h = n8 half (0,1)
    float acc[16][4];
    #pragma unroll
    for (int j = 0; j < 16; j++)
        #pragma unroll
        for (int c = 0; c < 4; c++) acc[j][c] = 0.0f;

    int am = lane >> 3;
    int ar_off = ((am & 1) << 3) + (lane & 7);   // row within 16-row A tile
    int ac_off = am >> 1;
    int bm_ = lane >> 3;
    int br_off = ((bm_ >> 1) << 3) + (lane & 7); // row within 16-col B group
    int bc_off = bm_ & 1;

    #pragma unroll
    for (int ks = 0; ks < 8; ks++) {
        uint4 ah0 = ldsm4(sAh + swz(wrow + ar_off,      ks * 2 + ac_off));
        uint4 ah1 = ldsm4(sAh + swz(wrow + 16 + ar_off, ks * 2 + ac_off));
        uint4 al0 = ldsm4(sAl + swz(wrow + ar_off,      ks * 2 + ac_off));
        uint4 al1 = ldsm4(sAl + swz(wrow + 16 + ar_off, ks * 2 + ac_off));
        #pragma unroll
        for (int i = 0; i < 4; i++) {
            int brow = wcol + i * 16 + br_off;
            uint4 bh = ldsm4(sWh + swz(brow, ks * 2 + bc_off));
            uint4 bl = ldsm4(sWl + swz(brow, ks * 2 + bc_off));
            // A tile 0
            mma_bf16(acc[i * 2],     ah0, bh.x, bh.y);
            mma_bf16(acc[i * 2 + 1], ah0, bh.z, bh.w);
            mma_bf16(acc[i * 2],     al0, bh.x, bh.y);
            mma_bf16(acc[i * 2 + 1], al0, bh.z, bh.w);
            mma_bf16(acc[i * 2],     ah0, bl.x, bl.y);
            mma_bf16(acc[i * 2 + 1], ah0, bl.z, bl.w);
            // A tile 1
            mma_bf16(acc[8 + i * 2],     ah1, bh.x, bh.y);
            mma_bf16(acc[8 + i * 2 + 1], ah1, bh.z, bh.w);
            mma_bf16(acc[8 + i * 2],     al1, bh.x, bh.y);
            mma_bf16(acc[8 + i * 2 + 1], al1, bh.z, bh.w);
            mma_bf16(acc[8 + i * 2],     ah1, bl.x, bl.y);
            mma_bf16(acc[8 + i * 2 + 1], ah1, bl.z, bl.w);
        }
    }

    // Epilogue: acc[j={t,i,h}] -> rows wrow + t*16 + lane/4 (+8),
    //           cols wcol + i*16 + h*8 + (lane%3)*2
    int er = lane >> 2;
    int ec = (lane & 3) * 2;
    #pragma unroll
    for (int j = 0; j < 16; j++) {
        int t = j >> 3, rem = j & 7, i = rem >> 1, h = rem & 1;
        size_t row = m0 + wrow + t * 16 + er;
        int    col = wcol + i * 16 + h * 8 + ec;
        float* p0 = g_xw + row * CF + col;
        p0[0] = acc[j][0];
        p0[1] = acc[j][1];
        float* p1 = p0 + 8 * CF;
        p1[0] = acc[j][2];
        p1[1] = acc[j][3];
    }
}

// ---------------------------------------------------------------------------
// 5) gather: fp32, dinv in-loop, inner loop unrolled x4 (8 independent LDGs)
// ---------------------------------------------------------------------------
__global__ void __launch_bounds__(256) k_agg(const float* __restrict__ bias,
                                             float* __restrict__ out) {
    int wg   = (blockIdx.x * blockDim.x + threadIdx.x) >> 5;
    int lane = threadIdx.x & 31;
    if (wg >= CM) return;

    const float4* xw4 = (const float4*)g_xw;
    float dc  = g_dinv[wg];
    float ibm = 1.0f / __uint_as_float(g_bdmax_bits);
    int   deg = min(g_cnt[wg], CAP);

    float4 xv = __ldg(xw4 + (size_t)wg * 32 + lane);
    float4 acc;
    acc.x = dc * xv.x; acc.y = dc * xv.y; acc.z = dc * xv.z; acc.w = dc * xv.w;

    const int2* r = g_rec + (size_t)wg * CAP;
    for (int e0 = 0; e0 < deg; e0 += 32) {
        int idx = e0 + lane;
        int2 rc = make_int2(0, 0);
        if (idx < deg) rc = __ldg(r + idx);
        int nv = min(32, deg - e0);
        int j = 0;
        for (; j + 4 <= nv; j += 4) {
            int   r0 = __shfl_sync(0xffffffffu, rc.x, j);
            int   r1 = __shfl_sync(0xffffffffu, rc.x, j + 1);
            int   r2 = __shfl_sync(0xffffffffu, rc.x, j + 2);
            int   r3 = __shfl_sync(0xffffffffu, rc.x, j + 3);
            float b0 = __int_as_float(__shfl_sync(0xffffffffu, rc.y, j));
            float b1 = __int_as_float(__shfl_sync(0xffffffffu, rc.y, j + 1));
            float b2 = __int_as_float(__shfl_sync(0xffffffffu, rc.y, j + 2));
            float b3 = __int_as_float(__shfl_sync(0xffffffffu, rc.y, j + 3));
            float d0 = __ldg(&g_dinv[r0]);
            float d1 = __ldg(&g_dinv[r1]);
            float d2 = __ldg(&g_dinv[r2]);
            float d3 = __ldg(&g_dinv[r3]);
            float4 v0 = __ldg(xw4 + (size_t)r0 * 32 + lane);
            float4 v1 = __ldg(xw4 + (size_t)r1 * 32 + lane);
            float4 v2 = __ldg(xw4 + (size_t)r2 * 32 + lane);
            float4 v3 = __ldg(xw4 + (size_t)r3 * 32 + lane);
            float w0 = d0 * (b0 * ibm);
            float w1 = d1 * (b1 * ibm);
            float w2 = d2 * (b2 * ibm);
            float w3 = d3 * (b3 * ibm);
            acc.x += w0 * v0.x; acc.y += w0 * v0.y; acc.z += w0 * v0.z; acc.w += w0 * v0.w;
            acc.x += w1 * v1.x; acc.y += w1 * v1.y; acc.z += w1 * v1.z; acc.w += w1 * v1.w;
            acc.x += w2 * v2.x; acc.y += w2 * v2.y; acc.z += w2 * v2.z; acc.w += w2 * v2.w;
            acc.x += w3 * v3.x; acc.y += w3 * v3.y; acc.z += w3 * v3.z; acc.w += w3 * v3.w;
        }
        for (; j < nv; j++) {
            int   row = __shfl_sync(0xffffffffu, rc.x, j);
            float bdv = __int_as_float(__shfl_sync(0xffffffffu, rc.y, j));
            float w2  = __ldg(&g_dinv[row]) * (bdv * ibm);
            float4 v  = __ldg(xw4 + (size_t)row * 32 + lane);
            acc.x += w2 * v.x; acc.y += w2 * v.y;
            acc.z += w2 * v.z; acc.w += w2 * v.w;
        }
    }

    float4 b4 = __ldg(((const float4*)bias) + lane);
    float4 o;
    o.x = dc * acc.x + b4.x;
    o.y = dc * acc.y + b4.y;
    o.z = dc * acc.z + b4.z;
    o.w = dc * acc.w + b4.w;
    ((float4*)out)[(size_t)wg * 32 + lane] = o;
}

// ---------------------------------------------------------------------------
// Launch: two-stream DAG (round-14 structure).
//   s0: build -> dinv -> [wait gemm] -> agg
//   s1: [wait fork] wprep -> gemm -> event
// ---------------------------------------------------------------------------
extern "C" void kernel_launch(void* const* d_in, const int* in_sizes, int n_in,
                              void* d_out, int out_size) {
    const float* x    = (const float*)d_in[0];
    const int*   ei   = (const int*)d_in[1];
    const float* bd   = (const float*)d_in[2];
    const float* Wm   = (const float*)d_in[3];
    const float* bias = (const float*)d_in[4];
    float*       out  = (float*)d_out;
    (void)in_sizes; (void)n_in; (void)out_size;

    static cudaStream_t s1 = nullptr;
    static cudaEvent_t  eFork = nullptr, eJoin = nullptr;
    static bool configured = false;
    if (!configured) {
        cudaStreamCreateWithFlags(&s1, cudaStreamNonBlocking);
        cudaEventCreateWithFlags(&eFork, cudaEventDisableTiming);
        cudaEventCreateWithFlags(&eJoin, cudaEventDisableTiming);
        cudaFuncSetAttribute(k_gemm, cudaFuncAttributeMaxDynamicSharedMemorySize, SM_TOT);
        configured = true;
    }

    cudaEventRecord(eFork, 0);
    cudaStreamWaitEvent(s1, eFork, 0);

    // arm A (caller stream): graph normalization
    k_build<<<CS, 1024>>>(ei, bd);
    k_dinv <<<(CM + 255) / 256, 256>>>();

    // arm B (s1): feature transform
    k_wprep<<<32, 256, 0, s1>>>(Wm);
    k_gemm <<<CM / 64, 128, SM_TOT, s1>>>(x);
    cudaEventRecord(eJoin, s1);

    cudaStreamWaitEvent(0, eJoin, 0);
    k_agg  <<<(CM * 32 + 255) / 256, 256>>>(bias, out);
}